// round 1
// baseline (speedup 1.0000x reference)
#include <cuda_runtime.h>
#include <cuda_bf16.h>
#include <math.h>

// ---------------- constants ----------------
#define Nb 16
#define CIN 32
#define COUT 128
#define IHW 224
#define OHW 112
#define HWF (OHW*OHW)        // 12544
#define NCLS 1000
#define KTOP 2
#define EPSV 1e-6f
#define THRV 0.35f

// output packing (float32): logits | boxes | labels | scores | valid
#define OFF_LOGITS 0
#define OFF_BOXES  (Nb*NCLS)                 // 16000
#define OFF_LABELS (OFF_BOXES + Nb*KTOP*4)   // 16128
#define OFF_SCORES (OFF_LABELS + Nb*KTOP)    // 16160
#define OFF_VALID  (OFF_SCORES + Nb*KTOP)    // 16192

// ---------------- scratch (static device memory; no allocs) ----------------
__device__ float g_A[(size_t)Nb*COUT*HWF];     // conv activations, ~103 MB
__device__ float g_S[Nb*COUT];                 // per-(n,c) spatial sums
__device__ int   g_labels[Nb*KTOP];
__device__ float g_w[KTOP*Nb*COUT];            // cam channel weights
__device__ float g_cam[(size_t)KTOP*Nb*HWF];   // small cams
__device__ int   g_cmin[KTOP*Nb];
__device__ int   g_cmax[KTOP*Nb];

// ---------------- conv 3x3 stride-2, pad (0,1)x(0,1) ----------------
// Block: one (n, oh, ow-tile of 28). 512 threads: cout = t&127, pixel group = t>>7 (7 px each).
// Weights chunked over cin (8 at a time) into smem, laid out [j][cout] padded to 129.
#define CCH 8
__global__ __launch_bounds__(512, 2)
void conv_kernel(const float* __restrict__ x, const float* __restrict__ Wc,
                 const float* __restrict__ bc)
{
    __shared__ float w_s[72*129];      // 8 cin * 9 taps, stride 129 to dodge conflicts
    __shared__ float in_s[CCH*3*57];   // 8 cin * 3 rows * 57 cols

    const int bx  = blockIdx.x;        // 0..3 (ow tiles of 28)
    const int oh  = blockIdx.y;        // 0..111
    const int n   = blockIdx.z;        // 0..15
    const int tid = threadIdx.x;
    const int cout = tid & 127;
    const int pg   = tid >> 7;         // 0..3
    const int owbase = bx * 28;

    float acc[7];
    const float b = bc[cout];
#pragma unroll
    for (int p = 0; p < 7; p++) acc[p] = b;

    for (int cc = 0; cc < CIN/CCH; cc++) {
        // weights: src Wc[cout][cin][kh][kw] (OIHW); coalesced 72-float runs per cout
        for (int s = tid; s < 128*72; s += 512) {
            int co = s / 72, j = s - co*72;
            w_s[j*129 + co] = Wc[co*288 + cc*72 + j];
        }
        // input rows oh*2..oh*2+2, cols owbase*2..+56; zero-pad OOB (pad lo=0, hi=1)
        for (int e = tid; e < CCH*3*57; e += 512) {
            int ci = e / 171; int rem = e - ci*171;
            int kh = rem / 57; int col = rem - kh*57;
            int ih = oh*2 + kh;
            int iw = owbase*2 + col;
            float v = 0.f;
            if (ih < IHW && iw < IHW)
                v = x[(((size_t)n*CIN + cc*CCH + ci)*IHW + ih)*IHW + iw];
            in_s[e] = v;
        }
        __syncthreads();
#pragma unroll
        for (int ci = 0; ci < CCH; ci++) {
#pragma unroll
            for (int kh = 0; kh < 3; kh++) {
                float xv[15];
                const float* row = &in_s[(ci*3 + kh)*57 + pg*14];
#pragma unroll
                for (int i = 0; i < 15; i++) xv[i] = row[i];
#pragma unroll
                for (int kw = 0; kw < 3; kw++) {
                    float wv = w_s[(ci*9 + kh*3 + kw)*129 + cout];
#pragma unroll
                    for (int p = 0; p < 7; p++)
                        acc[p] = fmaf(wv, xv[2*p + kw], acc[p]);
                }
            }
        }
        __syncthreads();
    }
    size_t base = (((size_t)n*COUT + cout)*OHW + oh)*OHW + owbase + pg*7;
#pragma unroll
    for (int p = 0; p < 7; p++) g_A[base + p] = acc[p];
}

// ---------------- per-(n,c) spatial sum ----------------
__global__ void sumA_kernel()
{
    int b = blockIdx.x;                // n*128 + c
    const float* p = g_A + (size_t)b * HWF;
    float s = 0.f;
    for (int i = threadIdx.x; i < HWF; i += 256) s += p[i];
    __shared__ float sh[256];
    sh[threadIdx.x] = s; __syncthreads();
    for (int off = 128; off; off >>= 1) {
        if (threadIdx.x < off) sh[threadIdx.x] += sh[threadIdx.x + off];
        __syncthreads();
    }
    if (threadIdx.x == 0) g_S[b] = sh[0];
}

// ---------------- logits = mean @ Wf.T + bf ----------------
__global__ void logits_kernel(const float* __restrict__ Wf,
                              const float* __restrict__ bf,
                              float* __restrict__ out)
{
    __shared__ float m[COUT];
    int n = blockIdx.x;
    if (threadIdx.x < COUT) m[threadIdx.x] = g_S[n*COUT + threadIdx.x] * (1.f/(float)HWF);
    __syncthreads();
    for (int cls = threadIdx.x; cls < NCLS; cls += blockDim.x) {
        const float* wr = Wf + (size_t)cls*COUT;
        float a = 0.f;
#pragma unroll 8
        for (int c = 0; c < COUT; c++) a = fmaf(m[c], wr[c], a);
        out[OFF_LOGITS + n*NCLS + cls] = a + bf[cls];
    }
}

// ---------------- top-2 per row (ties -> lower index first) ----------------
__device__ __forceinline__ bool gtpair(float v, int i, float v2, int i2) {
    return v > v2 || (v == v2 && i < i2);
}
__global__ void top2_kernel(const float* __restrict__ out)
{
    int n = blockIdx.x;
    const float* L = out + OFF_LOGITS + n*NCLS;
    int tid = threadIdx.x;
    float v1 = -3.4e38f, v2 = -3.4e38f;
    int i1 = 0x7fffffff, i2 = 0x7fffffff;
    for (int i = tid; i < NCLS; i += 256) {
        float v = L[i];
        if (gtpair(v, i, v1, i1)) { v2 = v1; i2 = i1; v1 = v; i1 = i; }
        else if (gtpair(v, i, v2, i2)) { v2 = v; i2 = i; }
    }
    __shared__ float sv1[256], sv2[256];
    __shared__ int   si1[256], si2[256];
    sv1[tid] = v1; si1[tid] = i1; sv2[tid] = v2; si2[tid] = i2;
    __syncthreads();
    for (int off = 128; off; off >>= 1) {
        if (tid < off) {
            float av1 = sv1[tid], av2 = sv2[tid];
            int   ai1 = si1[tid], ai2 = si2[tid];
            float bv1 = sv1[tid+off], bv2 = sv2[tid+off];
            int   bi1 = si1[tid+off], bi2 = si2[tid+off];
            float nv1, nv2; int ni1, ni2;
            if (gtpair(bv1, bi1, av1, ai1)) {
                nv1 = bv1; ni1 = bi1;
                if (gtpair(av1, ai1, bv2, bi2)) { nv2 = av1; ni2 = ai1; }
                else                            { nv2 = bv2; ni2 = bi2; }
            } else {
                nv1 = av1; ni1 = ai1;
                if (gtpair(bv1, bi1, av2, ai2)) { nv2 = bv1; ni2 = bi1; }
                else                            { nv2 = av2; ni2 = ai2; }
            }
            sv1[tid] = nv1; si1[tid] = ni1; sv2[tid] = nv2; si2[tid] = ni2;
        }
        __syncthreads();
    }
    if (tid == 0) { g_labels[n*KTOP] = si1[0]; g_labels[n*KTOP+1] = si2[0]; }
}

// ---------------- GradCAM++ channel weights (G constant over space) ----------------
__global__ void wcoef_kernel(const float* __restrict__ Wf)
{
    int n = blockIdx.x;
    int tid = threadIdx.x;           // 256: k = tid>>7, c = tid&127
    int k = tid >> 7, c = tid & 127;
    int lab = g_labels[n*KTOP + k];
    float g  = Wf[(size_t)lab*COUT + c] * (1.f/(float)HWF);
    float g2 = g * g;
    float denom = 2.f*g2 + g2*g*g_S[n*COUT + c] + EPSV;
    float alpha = g2 / denom;
    float wv = alpha * fmaxf(g, 0.f) * (float)HWF;
    g_w[(k*Nb + n)*COUT + c] = wv;
}

// ---------------- init min/max ----------------
__global__ void initmm_kernel()
{
    int t = threadIdx.x;
    if (t < KTOP*Nb) { g_cmin[t] = 0x7F800000; g_cmax[t] = 0; }
}

// ---------------- cam = relu(sum_c w*A), + per-map min/max ----------------
__global__ __launch_bounds__(128)
void cam_kernel()
{
    const int h = blockIdx.x;       // 0..111
    const int n = blockIdx.y;       // 0..15
    const int tid = threadIdx.x;    // 128, 112 active
    __shared__ float w0[COUT], w1[COUT];
    if (tid < COUT) {
        w0[tid] = g_w[(0*Nb + n)*COUT + tid];
        w1[tid] = g_w[(1*Nb + n)*COUT + tid];
    }
    __syncthreads();
    float a0 = 0.f, a1 = 0.f;
    const bool act = tid < OHW;
    if (act) {
        const float* Ap = g_A + ((size_t)n*COUT)*HWF + h*OHW + tid;
#pragma unroll 8
        for (int c = 0; c < COUT; c++) {
            float a = Ap[(size_t)c*HWF];
            a0 = fmaf(w0[c], a, a0);
            a1 = fmaf(w1[c], a, a1);
        }
        a0 = fmaxf(a0, 0.f); a1 = fmaxf(a1, 0.f);
        g_cam[(size_t)(0*Nb + n)*HWF + h*OHW + tid] = a0;
        g_cam[(size_t)(1*Nb + n)*HWF + h*OHW + tid] = a1;
    }
    // reduce min/max (non-negative floats: int-bit compare is order-preserving)
    float mn0 = act ? a0 : 3.4e38f, mx0 = act ? a0 : 0.f;
    float mn1 = act ? a1 : 3.4e38f, mx1 = act ? a1 : 0.f;
#pragma unroll
    for (int off = 16; off; off >>= 1) {
        mn0 = fminf(mn0, __shfl_xor_sync(0xFFFFFFFF, mn0, off));
        mx0 = fmaxf(mx0, __shfl_xor_sync(0xFFFFFFFF, mx0, off));
        mn1 = fminf(mn1, __shfl_xor_sync(0xFFFFFFFF, mn1, off));
        mx1 = fmaxf(mx1, __shfl_xor_sync(0xFFFFFFFF, mx1, off));
    }
    __shared__ float red[4][4];
    int wid = tid >> 5, lane = tid & 31;
    if (lane == 0) { red[wid][0]=mn0; red[wid][1]=mx0; red[wid][2]=mn1; red[wid][3]=mx1; }
    __syncthreads();
    if (tid == 0) {
        for (int wdx = 1; wdx < 4; wdx++) {
            mn0 = fminf(mn0, red[wdx][0]); mx0 = fmaxf(mx0, red[wdx][1]);
            mn1 = fminf(mn1, red[wdx][2]); mx1 = fmaxf(mx1, red[wdx][3]);
        }
        atomicMin(&g_cmin[0*Nb + n], __float_as_int(mn0));
        atomicMax(&g_cmax[0*Nb + n], __float_as_int(mx0));
        atomicMin(&g_cmin[1*Nb + n], __float_as_int(mn1));
        atomicMax(&g_cmax[1*Nb + n], __float_as_int(mx1));
    }
}

// ---------------- normalize + bilinear upsample + threshold + bbox/score ----------------
__global__ __launch_bounds__(256)
void final_kernel(float* __restrict__ out)
{
    const int m = blockIdx.x;        // k*16 + n
    const int k = m >> 4, n = m & 15;
    const float* C = g_cam + (size_t)m * HWF;
    const float mn = __int_as_float(g_cmin[m]);
    const float mx = __int_as_float(g_cmax[m]);
    const float inv = 1.f / ((mx - mn) + EPSV);
    const int tid = threadIdx.x;

    int lminx = 1 << 30, lminy = 1 << 30, lmaxx = -1, lmaxy = -1, lcnt = 0;
    float lsum = 0.f;
    for (int pix = tid; pix < IHW*IHW; pix += 256) {
        int oy = pix / IHW, ox = pix - oy*IHW;
        // half-pixel mapping, scale 0.5; edge renormalization == clamp
        float sx = 0.5f*ox - 0.25f;
        float sy = 0.5f*oy - 0.25f;
        float fxs = floorf(sx), fys = floorf(sy);
        int x0 = (int)fxs, y0 = (int)fys;
        float ax = sx - fxs, ay = sy - fys;
        int x0c = max(x0, 0), x1c = min(x0 + 1, OHW - 1);
        int y0c = max(y0, 0), y1c = min(y0 + 1, OHW - 1);
        float v00 = C[y0c*OHW + x0c], v01 = C[y0c*OHW + x1c];
        float v10 = C[y1c*OHW + x0c], v11 = C[y1c*OHW + x1c];
        float v = (1.f - ay)*((1.f - ax)*v00 + ax*v01)
                + ay       *((1.f - ax)*v10 + ax*v11);
        float nv = (v - mn) * inv;
        if (nv >= THRV) {
            lminx = min(lminx, ox); lmaxx = max(lmaxx, ox);
            lminy = min(lminy, oy); lmaxy = max(lmaxy, oy);
            lcnt++; lsum += nv;
        }
    }
    __shared__ int   rminx[256], rminy[256], rmaxx[256], rmaxy[256], rcnt[256];
    __shared__ float rsum[256];
    rminx[tid]=lminx; rminy[tid]=lminy; rmaxx[tid]=lmaxx; rmaxy[tid]=lmaxy;
    rcnt[tid]=lcnt; rsum[tid]=lsum;
    __syncthreads();
    for (int off = 128; off; off >>= 1) {
        if (tid < off) {
            rminx[tid] = min(rminx[tid], rminx[tid+off]);
            rminy[tid] = min(rminy[tid], rminy[tid+off]);
            rmaxx[tid] = max(rmaxx[tid], rmaxx[tid+off]);
            rmaxy[tid] = max(rmaxy[tid], rmaxy[tid+off]);
            rcnt[tid] += rcnt[tid+off];
            rsum[tid] += rsum[tid+off];
        }
        __syncthreads();
    }
    if (tid == 0) {
        int cnt = rcnt[0];
        bool valid = cnt > 0;
        int ob = OFF_BOXES + (n*KTOP + k)*4;
        out[ob+0] = valid ? (float)rminx[0] : -1.f;
        out[ob+1] = valid ? (float)rminy[0] : -1.f;
        out[ob+2] = valid ? (float)rmaxx[0] : -1.f;
        out[ob+3] = valid ? (float)rmaxy[0] : -1.f;
        out[OFF_LABELS + n*KTOP + k] = (float)g_labels[n*KTOP + k];
        out[OFF_SCORES + n*KTOP + k] = valid ? rsum[0] / (float)cnt : 0.f;
        out[OFF_VALID  + n*KTOP + k] = valid ? 1.f : 0.f;
    }
}

// ---------------- launch ----------------
extern "C" void kernel_launch(void* const* d_in, const int* in_sizes, int n_in,
                              void* d_out, int out_size)
{
    const float* x  = (const float*)d_in[0];
    const float* Wc = (const float*)d_in[1];
    const float* bc = (const float*)d_in[2];
    const float* Wf = (const float*)d_in[3];
    const float* bf = (const float*)d_in[4];
    float* out = (float*)d_out;

    conv_kernel<<<dim3(4, OHW, Nb), 512>>>(x, Wc, bc);
    sumA_kernel<<<Nb*COUT, 256>>>();
    logits_kernel<<<Nb, 256>>>(Wf, bf, out);
    top2_kernel<<<Nb, 256>>>(out);
    wcoef_kernel<<<Nb, 256>>>(Wf);
    initmm_kernel<<<1, 64>>>();
    cam_kernel<<<dim3(OHW, Nb), 128>>>();
    final_kernel<<<KTOP*Nb, 256>>>(out);
}

// round 4
// speedup vs baseline: 1.1151x; 1.1151x over previous
#include <cuda_runtime.h>
#include <cuda_bf16.h>
#include <math.h>

// ---------------- constants ----------------
#define Nb 16
#define CIN 32
#define COUT 128
#define IHW 224
#define OHW 112
#define HWF (OHW*OHW)        // 12544
#define NCLS 1000
#define KTOP 2
#define EPSV 1e-6f
#define THRV 0.35f
#define CCH 4                // cin per chunk in conv

// output packing (float32): logits | boxes | labels | scores | valid
#define OFF_LOGITS 0
#define OFF_BOXES  (Nb*NCLS)                 // 16000
#define OFF_LABELS (OFF_BOXES + Nb*KTOP*4)   // 16128
#define OFF_SCORES (OFF_LABELS + Nb*KTOP)    // 16160
#define OFF_VALID  (OFF_SCORES + Nb*KTOP)    // 16192

// packed f32x2 FMA (sm_100 family): acc += a * b elementwise on 2-wide fp32
#define FMA2(accv, av, bv) \
    asm("fma.rn.f32x2 %0, %1, %2, %0;" : "+l"(accv) : "l"(av), "l"(bv))

// ---------------- scratch (static device memory; no allocs) ----------------
__device__ float g_A[(size_t)Nb*COUT*HWF];     // conv activations, ~103 MB
__device__ float g_S[Nb*COUT];                 // per-(n,c) spatial sums
__device__ int   g_labels[Nb*KTOP];
__device__ float g_w[KTOP*Nb*COUT];            // cam channel weights
__device__ float g_cam[(size_t)KTOP*Nb*HWF];   // small cams
__device__ int   g_cmin[KTOP*Nb];
__device__ int   g_cmax[KTOP*Nb];
__device__ __align__(16) float g_wpack[2*8*CCH*9*64];  // packed cout-pair weights
// bbox accumulators (integer -> deterministic)
__device__ int g_bminx[KTOP*Nb], g_bminy[KTOP*Nb], g_bmaxx[KTOP*Nb], g_bmaxy[KTOP*Nb];
__device__ int g_bcnt[KTOP*Nb];
__device__ unsigned long long g_bsum[KTOP*Nb]; // fixed-point sum (2^20)

// ---------------- weight repack: Wc[cout][cin][3][3] -> pairs over cout ----------------
// layout: g_wpack[cc][(ci*9+tap)*64 + cp] as float2 = (Wc[2cp][...], Wc[2cp+1][...])
__global__ void prep_kernel(const float* __restrict__ Wc)
{
    int idx = blockIdx.x*256 + threadIdx.x;
    if (idx >= 8*CCH*9*64) return;
    int cc  = idx / (CCH*9*64);
    int rem = idx % (CCH*9*64);
    int cit = rem / 64;            // ci*9 + tap
    int cp  = rem % 64;
    int ci  = cit / 9, tap = cit % 9;
    int j = (cc*CCH + ci)*9 + tap; // offset within a cout's 288-run
    g_wpack[2*idx]   = Wc[(size_t)(2*cp)*288 + j];
    g_wpack[2*idx+1] = Wc[(size_t)(2*cp+1)*288 + j];
}

// ---------------- conv 3x3 stride-2, pad (0,1)x(0,1), packed f32x2 ----------------
// Block = (oh, n): full output row, all 128 couts.
// 448 threads: cp = tid&63 (couts 2cp,2cp+1), pg = tid>>6 (0..6), pixels pg*16..+15.
__global__ __launch_bounds__(448)
void conv_kernel(const float* __restrict__ x, const float* __restrict__ bc)
{
    __shared__ __align__(16) float2 in2[CCH*3*226];   // duplicated (v,v) pairs
    __shared__ __align__(16) float2 w_s[CCH*9*64];    // packed weight pairs

    const int oh = blockIdx.x;
    const int n  = blockIdx.y;
    const int tid = threadIdx.x;
    const int cp = tid & 63;
    const int pg = tid >> 6;

    unsigned long long acc[16];
    {
        float2 bb = *(const float2*)(bc + 2*cp);
        unsigned long long b = *(unsigned long long*)&bb;
#pragma unroll
        for (int p = 0; p < 16; p++) acc[p] = b;
    }

    for (int cc = 0; cc < CIN/CCH; cc++) {
        // weights: straight vector copy of the packed image for this chunk
        {
            const float4* wsrc = (const float4*)g_wpack + cc*(CCH*9*64/2);
            float4* wdst = (float4*)w_s;
            for (int e = tid; e < CCH*9*64/2; e += 448) wdst[e] = wsrc[e];
        }
        // input: rows 2*oh+kh, full width, duplicated pairs, zero-padded OOB
        for (int e = tid; e < CCH*3*226; e += 448) {
            int ci  = e / (3*226);
            int rem = e - ci*(3*226);
            int kh  = rem / 226;
            int col = rem - kh*226;
            int ih  = 2*oh + kh;
            float v = 0.f;
            if (ih < IHW && col < IHW)
                v = x[(((size_t)n*CIN + cc*CCH + ci)*IHW + ih)*IHW + col];
            in2[e] = make_float2(v, v);
        }
        __syncthreads();

        const unsigned long long* wsp = (const unsigned long long*)w_s + cp;
#pragma unroll
        for (int ci = 0; ci < CCH; ci++) {
#pragma unroll
            for (int kh = 0; kh < 3; kh++) {
                const ulonglong2* rp =
                    (const ulonglong2*)(in2 + (ci*3 + kh)*226) + pg*16;
                unsigned long long w0 = wsp[(size_t)(ci*9 + kh*3 + 0)*64];
                unsigned long long w1 = wsp[(size_t)(ci*9 + kh*3 + 1)*64];
                unsigned long long w2 = wsp[(size_t)(ci*9 + kh*3 + 2)*64];
                ulonglong2 q = rp[0];              // (pair x_{2p}, pair x_{2p+1})
                FMA2(acc[0], w0, q.x);
                FMA2(acc[0], w1, q.y);
#pragma unroll
                for (int p = 1; p < 16; p++) {
                    ulonglong2 t = rp[p];
                    FMA2(acc[p-1], w2, t.x);
                    FMA2(acc[p],   w0, t.x);
                    FMA2(acc[p],   w1, t.y);
                }
                ulonglong2 z = rp[16];
                FMA2(acc[15], w2, z.x);
            }
        }
        __syncthreads();
    }

    // store: 16 consecutive pixels per cout -> 4x STG.128 each, unpacked in place
    size_t base0 = (((size_t)n*COUT + 2*cp)*OHW + oh)*OHW + pg*16;
#pragma unroll
    for (int g = 0; g < 4; g++) {
        float2 u0 = *(float2*)&acc[4*g+0];
        float2 u1 = *(float2*)&acc[4*g+1];
        float2 u2 = *(float2*)&acc[4*g+2];
        float2 u3 = *(float2*)&acc[4*g+3];
        *(float4*)&g_A[base0 + 4*g]       = make_float4(u0.x, u1.x, u2.x, u3.x);
        *(float4*)&g_A[base0 + HWF + 4*g] = make_float4(u0.y, u1.y, u2.y, u3.y);
    }
}

// ---------------- per-(n,c) spatial sum ----------------
__global__ void sumA_kernel()
{
    int b = blockIdx.x;                // n*128 + c
    const float* p = g_A + (size_t)b * HWF;
    float s = 0.f;
    for (int i = threadIdx.x; i < HWF; i += 256) s += p[i];
    __shared__ float sh[256];
    sh[threadIdx.x] = s; __syncthreads();
    for (int off = 128; off; off >>= 1) {
        if (threadIdx.x < off) sh[threadIdx.x] += sh[threadIdx.x + off];
        __syncthreads();
    }
    if (threadIdx.x == 0) g_S[b] = sh[0];
}

// ---------------- logits = mean @ Wf.T + bf ----------------
__global__ void logits_kernel(const float* __restrict__ Wf,
                              const float* __restrict__ bf,
                              float* __restrict__ out)
{
    __shared__ float m[COUT];
    int n = blockIdx.x;
    if (threadIdx.x < COUT) m[threadIdx.x] = g_S[n*COUT + threadIdx.x] * (1.f/(float)HWF);
    __syncthreads();
    for (int cls = threadIdx.x; cls < NCLS; cls += blockDim.x) {
        const float* wr = Wf + (size_t)cls*COUT;
        float a = 0.f;
#pragma unroll 8
        for (int c = 0; c < COUT; c++) a = fmaf(m[c], wr[c], a);
        out[OFF_LOGITS + n*NCLS + cls] = a + bf[cls];
    }
}

// ---------------- top-2 per row (ties -> lower index first) ----------------
__device__ __forceinline__ bool gtpair(float v, int i, float v2, int i2) {
    return v > v2 || (v == v2 && i < i2);
}
__global__ void top2_kernel(const float* __restrict__ out)
{
    int n = blockIdx.x;
    const float* L = out + OFF_LOGITS + n*NCLS;
    int tid = threadIdx.x;
    float v1 = -3.4e38f, v2 = -3.4e38f;
    int i1 = 0x7fffffff, i2 = 0x7fffffff;
    for (int i = tid; i < NCLS; i += 256) {
        float v = L[i];
        if (gtpair(v, i, v1, i1)) { v2 = v1; i2 = i1; v1 = v; i1 = i; }
        else if (gtpair(v, i, v2, i2)) { v2 = v; i2 = i; }
    }
    __shared__ float sv1[256], sv2[256];
    __shared__ int   si1[256], si2[256];
    sv1[tid] = v1; si1[tid] = i1; sv2[tid] = v2; si2[tid] = i2;
    __syncthreads();
    for (int off = 128; off; off >>= 1) {
        if (tid < off) {
            float av1 = sv1[tid], av2 = sv2[tid];
            int   ai1 = si1[tid], ai2 = si2[tid];
            float bv1 = sv1[tid+off], bv2 = sv2[tid+off];
            int   bi1 = si1[tid+off], bi2 = si2[tid+off];
            float nv1, nv2; int ni1, ni2;
            if (gtpair(bv1, bi1, av1, ai1)) {
                nv1 = bv1; ni1 = bi1;
                if (gtpair(av1, ai1, bv2, bi2)) { nv2 = av1; ni2 = ai1; }
                else                            { nv2 = bv2; ni2 = bi2; }
            } else {
                nv1 = av1; ni1 = ai1;
                if (gtpair(bv1, bi1, av2, ai2)) { nv2 = bv1; ni2 = bi1; }
                else                            { nv2 = av2; ni2 = ai2; }
            }
            sv1[tid] = nv1; si1[tid] = ni1; sv2[tid] = nv2; si2[tid] = ni2;
        }
        __syncthreads();
    }
    if (tid == 0) { g_labels[n*KTOP] = si1[0]; g_labels[n*KTOP+1] = si2[0]; }
}

// ---------------- GradCAM++ channel weights (G constant over space) ----------------
__global__ void wcoef_kernel(const float* __restrict__ Wf)
{
    int n = blockIdx.x;
    int tid = threadIdx.x;           // 256: k = tid>>7, c = tid&127
    int k = tid >> 7, c = tid & 127;
    int lab = g_labels[n*KTOP + k];
    float g  = Wf[(size_t)lab*COUT + c] * (1.f/(float)HWF);
    float g2 = g * g;
    float denom = 2.f*g2 + g2*g*g_S[n*COUT + c] + EPSV;
    float alpha = g2 / denom;
    float wv = alpha * fmaxf(g, 0.f) * (float)HWF;
    g_w[(k*Nb + n)*COUT + c] = wv;
}

// ---------------- init accumulators ----------------
__global__ void init_kernel()
{
    int t = threadIdx.x;
    if (t < KTOP*Nb) {
        g_cmin[t] = 0x7F800000; g_cmax[t] = 0;
        g_bminx[t] = 1 << 30; g_bminy[t] = 1 << 30;
        g_bmaxx[t] = -1;      g_bmaxy[t] = -1;
        g_bcnt[t] = 0;        g_bsum[t] = 0ull;
    }
}

// ---------------- cam = relu(sum_c w*A), + per-map min/max ----------------
__global__ __launch_bounds__(128)
void cam_kernel()
{
    const int h = blockIdx.x;       // 0..111
    const int n = blockIdx.y;       // 0..15
    const int tid = threadIdx.x;    // 128, 112 active
    __shared__ float w0[COUT], w1[COUT];
    if (tid < COUT) {
        w0[tid] = g_w[(0*Nb + n)*COUT + tid];
        w1[tid] = g_w[(1*Nb + n)*COUT + tid];
    }
    __syncthreads();
    float a0 = 0.f, a1 = 0.f;
    const bool act = tid < OHW;
    if (act) {
        const float* Ap = g_A + ((size_t)n*COUT)*HWF + h*OHW + tid;
#pragma unroll 8
        for (int c = 0; c < COUT; c++) {
            float a = Ap[(size_t)c*HWF];
            a0 = fmaf(w0[c], a, a0);
            a1 = fmaf(w1[c], a, a1);
        }
        a0 = fmaxf(a0, 0.f); a1 = fmaxf(a1, 0.f);
        g_cam[(size_t)(0*Nb + n)*HWF + h*OHW + tid] = a0;
        g_cam[(size_t)(1*Nb + n)*HWF + h*OHW + tid] = a1;
    }
    float mn0 = act ? a0 : 3.4e38f, mx0 = act ? a0 : 0.f;
    float mn1 = act ? a1 : 3.4e38f, mx1 = act ? a1 : 0.f;
#pragma unroll
    for (int off = 16; off; off >>= 1) {
        mn0 = fminf(mn0, __shfl_xor_sync(0xFFFFFFFF, mn0, off));
        mx0 = fmaxf(mx0, __shfl_xor_sync(0xFFFFFFFF, mx0, off));
        mn1 = fminf(mn1, __shfl_xor_sync(0xFFFFFFFF, mn1, off));
        mx1 = fmaxf(mx1, __shfl_xor_sync(0xFFFFFFFF, mx1, off));
    }
    __shared__ float red[4][4];
    int wid = tid >> 5, lane = tid & 31;
    if (lane == 0) { red[wid][0]=mn0; red[wid][1]=mx0; red[wid][2]=mn1; red[wid][3]=mx1; }
    __syncthreads();
    if (tid == 0) {
        for (int wdx = 1; wdx < 4; wdx++) {
            mn0 = fminf(mn0, red[wdx][0]); mx0 = fmaxf(mx0, red[wdx][1]);
            mn1 = fminf(mn1, red[wdx][2]); mx1 = fmaxf(mx1, red[wdx][3]);
        }
        atomicMin(&g_cmin[0*Nb + n], __float_as_int(mn0));
        atomicMax(&g_cmax[0*Nb + n], __float_as_int(mx0));
        atomicMin(&g_cmin[1*Nb + n], __float_as_int(mn1));
        atomicMax(&g_cmax[1*Nb + n], __float_as_int(mx1));
    }
}

// ---------------- normalize + upsample + threshold + bbox accumulate ----------------
// grid = (32 maps, 8 row-groups), 256 threads; integer/fixed-point atomics (deterministic)
__global__ __launch_bounds__(256)
void final_kernel()
{
    const int m  = blockIdx.x;       // k*16 + n
    const int rg = blockIdx.y;       // 0..7 -> rows rg*28 .. +27
    const float* C = g_cam + (size_t)m * HWF;
    const float mn = __int_as_float(g_cmin[m]);
    const float mx = __int_as_float(g_cmax[m]);
    const float inv = 1.f / ((mx - mn) + EPSV);
    const int tid = threadIdx.x;

    int lminx = 1 << 30, lminy = 1 << 30, lmaxx = -1, lmaxy = -1, lcnt = 0;
    unsigned long long lsum = 0ull;
    // 28 rows x 224 cols; thread strides columns-within-row: 224 = 256-32,
    // iterate (row, col) directly to avoid div/mod in the loop
    for (int row = 0; row < 28; row++) {
        int oy = rg*28 + row;
        float sy = 0.5f*oy - 0.25f;
        float fys = floorf(sy);
        int y0 = (int)fys;
        float ay = sy - fys;
        int y0c = max(y0, 0), y1c = min(y0 + 1, OHW - 1);
        const float* r0 = C + y0c*OHW;
        const float* r1 = C + y1c*OHW;
        for (int ox = tid; ox < IHW; ox += 256) {
            float sx = 0.5f*ox - 0.25f;
            float fxs = floorf(sx);
            int x0 = (int)fxs;
            float ax = sx - fxs;
            int x0c = max(x0, 0), x1c = min(x0 + 1, OHW - 1);
            float v00 = r0[x0c], v01 = r0[x1c];
            float v10 = r1[x0c], v11 = r1[x1c];
            float v = (1.f - ay)*((1.f - ax)*v00 + ax*v01)
                    + ay       *((1.f - ax)*v10 + ax*v11);
            float nv = (v - mn) * inv;
            if (nv >= THRV) {
                lminx = min(lminx, ox); lmaxx = max(lmaxx, ox);
                lminy = min(lminy, oy); lmaxy = max(lmaxy, oy);
                lcnt++;
                lsum += (unsigned long long)(long long)(nv * 1048576.f + 0.5f);
            }
        }
    }
    __shared__ int   rminx[256], rminy[256], rmaxx[256], rmaxy[256], rcnt[256];
    __shared__ unsigned long long rsum[256];
    rminx[tid]=lminx; rminy[tid]=lminy; rmaxx[tid]=lmaxx; rmaxy[tid]=lmaxy;
    rcnt[tid]=lcnt; rsum[tid]=lsum;
    __syncthreads();
    for (int off = 128; off; off >>= 1) {
        if (tid < off) {
            rminx[tid] = min(rminx[tid], rminx[tid+off]);
            rminy[tid] = min(rminy[tid], rminy[tid+off]);
            rmaxx[tid] = max(rmaxx[tid], rmaxx[tid+off]);
            rmaxy[tid] = max(rmaxy[tid], rmaxy[tid+off]);
            rcnt[tid] += rcnt[tid+off];
            rsum[tid] += rsum[tid+off];
        }
        __syncthreads();
    }
    if (tid == 0) {
        atomicMin(&g_bminx[m], rminx[0]);
        atomicMin(&g_bminy[m], rminy[0]);
        atomicMax(&g_bmaxx[m], rmaxx[0]);
        atomicMax(&g_bmaxy[m], rmaxy[0]);
        atomicAdd(&g_bcnt[m], rcnt[0]);
        atomicAdd(&g_bsum[m], rsum[0]);
    }
}

// ---------------- write boxes/labels/scores/valid ----------------
__global__ void finalize_kernel(float* __restrict__ out)
{
    int m = threadIdx.x;             // k*16 + n
    if (m >= KTOP*Nb) return;
    int k = m >> 4, n = m & 15;
    int cnt = g_bcnt[m];
    bool valid = cnt > 0;
    int ob = OFF_BOXES + (n*KTOP + k)*4;
    out[ob+0] = valid ? (float)g_bminx[m] : -1.f;
    out[ob+1] = valid ? (float)g_bminy[m] : -1.f;
    out[ob+2] = valid ? (float)g_bmaxx[m] : -1.f;
    out[ob+3] = valid ? (float)g_bmaxy[m] : -1.f;
    out[OFF_LABELS + n*KTOP + k] = (float)g_labels[n*KTOP + k];
    out[OFF_SCORES + n*KTOP + k] =
        valid ? (float)((double)g_bsum[m] * (1.0/1048576.0) / (double)cnt) : 0.f;
    out[OFF_VALID  + n*KTOP + k] = valid ? 1.f : 0.f;
}

// ---------------- launch ----------------
extern "C" void kernel_launch(void* const* d_in, const int* in_sizes, int n_in,
                              void* d_out, int out_size)
{
    const float* x  = (const float*)d_in[0];
    const float* Wc = (const float*)d_in[1];
    const float* bc = (const float*)d_in[2];
    const float* Wf = (const float*)d_in[3];
    const float* bf = (const float*)d_in[4];
    float* out = (float*)d_out;

    prep_kernel<<<72, 256>>>(Wc);
    conv_kernel<<<dim3(OHW, Nb), 448>>>(x, bc);
    sumA_kernel<<<Nb*COUT, 256>>>();
    logits_kernel<<<Nb, 256>>>(Wf, bf, out);
    top2_kernel<<<Nb, 256>>>(out);
    wcoef_kernel<<<Nb, 256>>>(Wf);
    init_kernel<<<1, 64>>>();
    cam_kernel<<<dim3(OHW, Nb), 128>>>();
    final_kernel<<<dim3(KTOP*Nb, 8), 256>>>();
    finalize_kernel<<<1, 32>>>(out);
}